// round 1
// baseline (speedup 1.0000x reference)
#include <cuda_runtime.h>
#include <cuda_bf16.h>
#include <math.h>

#define Bn 8
#define Tn 512
#define Cn 8
#define Fn 257
#define An 320
#define BF (Bn*Fn)   // 2056

// ---------------- scratch (static device globals; no allocation) ----------------
__device__ float2 g_dataT[(size_t)Bn*Fn*Cn*Tn];   // (B,F,C,T) complex, 67.4 MB
__device__ float2 g_psd_s[(size_t)BF*Cn*Cn];      // (B,F,C,C)
__device__ float2 g_psd_n[(size_t)BF*Cn*Cn];
__device__ float  g_eval[Bn*Cn];
__device__ float  g_u[Bn*Cn];
__device__ float2 g_ws[(size_t)BF*Cn];            // (B,F,C)

// Hermitian pair tables (c<=e), 36 pairs
__constant__ unsigned char cP[36] = {0,0,0,0,0,0,0,0, 1,1,1,1,1,1,1, 2,2,2,2,2,2,
                                     3,3,3,3,3, 4,4,4,4, 5,5,5, 6,6, 7};
__constant__ unsigned char cE[36] = {0,1,2,3,4,5,6,7, 1,2,3,4,5,6,7, 2,3,4,5,6,7,
                                     3,4,5,6,7, 4,5,6,7, 5,6,7, 6,7, 7};

// ---------------- kernel 1: transpose (B,T,C,F) -> (B,F,C,T) float2 ----------------
__global__ void k_transpose(const float* __restrict__ dr, const float* __restrict__ di) {
    __shared__ float tr[32][33];
    __shared__ float ti[32][33];
    int bc = blockIdx.z;
    int b = bc >> 3, c = bc & 7;
    int f0 = blockIdx.x * 32, t0 = blockIdx.y * 32;
    int tx = threadIdx.x, ty = threadIdx.y;      // (32,8)

    #pragma unroll
    for (int r = 0; r < 32; r += 8) {
        int t = t0 + ty + r;
        int f = f0 + tx;
        if (f < Fn) {
            size_t idx = ((size_t)(b*Tn + t)*Cn + c)*Fn + f;
            tr[ty + r][tx] = dr[idx];
            ti[ty + r][tx] = di[idx];
        }
    }
    __syncthreads();
    #pragma unroll
    for (int r = 0; r < 32; r += 8) {
        int f = f0 + ty + r;
        int t = t0 + tx;
        if (f < Fn) {
            size_t o = ((size_t)(b*Fn + f)*Cn + c)*Tn + t;
            g_dataT[o] = make_float2(tr[tx][ty + r], ti[tx][ty + r]);
        }
    }
}

// ---------------- kernel 2: PSD per (b,f). 288 threads ----------------
__global__ __launch_bounds__(288) void k_psd(const float* __restrict__ ms,
                                             const float* __restrict__ mn) {
    __shared__ float2 xs[Cn][Tn];   // 32 KB
    __shared__ float  m0[Tn];       // speech mask weights
    __shared__ float  m1[Tn];       // noise mask weights
    __shared__ float  r0s[9], r1s[9];
    __shared__ float  sInv0, sInv1;

    int bf = blockIdx.x;
    int tid = threadIdx.x;

    const float* msp = ms + (size_t)bf * Cn * Tn;
    const float* mnp = mn + (size_t)bf * Cn * Tn;

    // masks: mean over c, then normalize over t
    float tot0 = 0.f, tot1 = 0.f;
    for (int t = tid; t < Tn; t += 288) {
        float s0 = 0.f, s1 = 0.f;
        #pragma unroll
        for (int c = 0; c < Cn; c++) { s0 += msp[c*Tn + t]; s1 += mnp[c*Tn + t]; }
        s0 *= 0.125f; s1 *= 0.125f;
        m0[t] = s0; m1[t] = s1;
        tot0 += s0; tot1 += s1;
    }
    // load x tile while reduce is in flight
    const float2* xp = g_dataT + (size_t)bf * Cn * Tn;
    for (int i = tid; i < Cn*Tn; i += 288) ((float2*)xs)[i] = xp[i];

    #pragma unroll
    for (int o = 16; o; o >>= 1) {
        tot0 += __shfl_xor_sync(0xffffffffu, tot0, o);
        tot1 += __shfl_xor_sync(0xffffffffu, tot1, o);
    }
    int w = tid >> 5, lane = tid & 31;
    if (lane == 0) { r0s[w] = tot0; r1s[w] = tot1; }
    __syncthreads();
    if (tid == 0) {
        float a = 0.f, bsum = 0.f;
        #pragma unroll
        for (int k = 0; k < 9; k++) { a += r0s[k]; bsum += r1s[k]; }
        sInv0 = 1.f / (a + 1e-15f);
        sInv1 = 1.f / (bsum + 1e-15f);
    }
    __syncthreads();
    float iv0 = sInv0, iv1 = sInv1;
    for (int t = tid; t < Tn; t += 288) { m0[t] *= iv0; m1[t] *= iv1; }
    __syncthreads();

    // 36 pair tasks x 8 subthreads; each accumulates BOTH masks (shared products)
    int task = tid >> 3;     // 0..35
    int sub  = tid & 7;
    int c = cP[task], e = cE[task];
    float asr = 0.f, asi = 0.f, anr = 0.f, ani = 0.f;
    for (int t = sub; t < Tn; t += 8) {
        float2 xc = xs[c][t];
        float2 xe = xs[e][t];
        float pr = xc.x*xe.x + xc.y*xe.y;
        float pi = xc.y*xe.x - xc.x*xe.y;
        float w0 = m0[t], w1 = m1[t];
        asr += w0*pr; asi += w0*pi;
        anr += w1*pr; ani += w1*pi;
    }
    #pragma unroll
    for (int o = 1; o < 8; o <<= 1) {
        asr += __shfl_xor_sync(0xffffffffu, asr, o);
        asi += __shfl_xor_sync(0xffffffffu, asi, o);
        anr += __shfl_xor_sync(0xffffffffu, anr, o);
        ani += __shfl_xor_sync(0xffffffffu, ani, o);
    }
    if (sub == 0) {
        size_t base = (size_t)bf * 64;
        g_psd_s[base + c*8 + e] = make_float2(asr,  asi);
        g_psd_s[base + e*8 + c] = make_float2(asr, -asi);
        g_psd_n[base + c*8 + e] = make_float2(anr,  ani);
        g_psd_n[base + e*8 + c] = make_float2(anr, -ani);
    }
}

// ---------------- kernel 3: attention MLP -> e[b,c]. 64 blocks x 320 threads --------
__global__ __launch_bounds__(An) void k_att(const float* __restrict__ mlp_w,
                                            const float* __restrict__ mlp_b,
                                            const float* __restrict__ gvw,
                                            const float* __restrict__ gvb) {
    __shared__ float feat[Fn];
    __shared__ float red[10];
    int b = blockIdx.x >> 3, c = blockIdx.x & 7;
    int tid = threadIdx.x;

    if (tid < Fn) {
        const float2* p = g_psd_s + ((size_t)(b*Fn + tid))*64 + c*8;
        float sr = 0.f, si = 0.f;
        #pragma unroll
        for (int e = 0; e < 8; e++) {
            if (e != c) { sr += p[e].x; si += p[e].y; }
        }
        feat[tid] = sqrtf(sr*sr + si*si) * (1.0f/7.0f);
    }
    __syncthreads();

    float dot = 0.f;
    for (int f = 0; f < Fn; f++) dot += feat[f] * mlp_w[f*An + tid];
    float h = tanhf(dot + mlp_b[tid]);
    float part = h * gvw[tid];

    #pragma unroll
    for (int o = 16; o; o >>= 1) part += __shfl_xor_sync(0xffffffffu, part, o);
    int w = tid >> 5, lane = tid & 31;
    if (lane == 0) red[w] = part;
    __syncthreads();
    if (tid == 0) {
        float s = 0.f;
        #pragma unroll
        for (int k = 0; k < 10; k++) s += red[k];
        g_eval[blockIdx.x] = s + gvb[0];
    }
}

// ---------------- kernel 4: softmax over channels. 1 block x 64 threads --------
__global__ void k_softmax() {
    int tid = threadIdx.x;                 // b = tid/8, c = tid%8
    float v = 2.0f * g_eval[tid];
    float mx = v;
    #pragma unroll
    for (int o = 1; o < 8; o <<= 1) mx = fmaxf(mx, __shfl_xor_sync(0xffffffffu, mx, o));
    float ex = expf(v - mx);
    float s = ex;
    #pragma unroll
    for (int o = 1; o < 8; o <<= 1) s += __shfl_xor_sync(0xffffffffu, s, o);
    g_u[tid] = ex / s;
}

// ---------------- kernel 5: MVDR solve per (b,f). 128 threads (8x16 augmented) ------
__global__ __launch_bounds__(128) void k_mvdr() {
    __shared__ double ar[8][16];
    __shared__ double ai[8][16];
    __shared__ double trr, tri;
    int bf = blockIdx.x;
    int b = bf / Fn;
    int tid = threadIdx.x;
    int i = tid >> 4, j = tid & 15;

    float2 v = (j < 8) ? g_psd_n[(size_t)bf*64 + i*8 + j]
                       : g_psd_s[(size_t)bf*64 + i*8 + (j - 8)];
    ar[i][j] = (double)v.x;
    ai[i][j] = (double)v.y;
    __syncthreads();

    // Gauss-Jordan on [N | S] -> right half becomes inv(N) @ S
    for (int k = 0; k < 8; k++) {
        double pr = ar[k][k], pim = ai[k][k];
        double dd = pr*pr + pim*pim;
        double qr = pr/dd, qi = -pim/dd;
        __syncthreads();
        if (i == k) {
            double xr = ar[k][j], xi = ai[k][j];
            ar[k][j] = xr*qr - xi*qi;
            ai[k][j] = xr*qi + xi*qr;
        }
        __syncthreads();
        double fr = ar[i][k], fi = ai[i][k];
        __syncthreads();
        if (i != k) {
            double gr = ar[k][j], gi = ai[k][j];
            ar[i][j] -= fr*gr - fi*gi;
            ai[i][j] -= fr*gi + fi*gr;
        }
        __syncthreads();
    }

    if (tid == 0) {
        double sr = 0.0, si = 0.0;
        #pragma unroll
        for (int c2 = 0; c2 < 8; c2++) { sr += ar[c2][8 + c2]; si += ai[c2][8 + c2]; }
        trr = sr + 1e-15;
        tri = si;
    }
    __syncthreads();
    if (tid < 8) {
        double sr = 0.0, si = 0.0;
        #pragma unroll
        for (int c2 = 0; c2 < 8; c2++) {
            double uu = (double)g_u[b*8 + c2];
            sr += ar[tid][8 + c2] * uu;
            si += ai[tid][8 + c2] * uu;
        }
        double dd = trr*trr + tri*tri;
        double wr = (sr*trr + si*tri) / dd;
        double wi = (si*trr - sr*tri) / dd;
        g_ws[(size_t)bf*8 + tid] = make_float2((float)wr, (float)wi);
    }
}

// ---------------- kernel 6: beamforming -> output (B,T,F,2) ----------------
#define TCH 8
__global__ __launch_bounds__(288) void k_beam(const float* __restrict__ dr,
                                              const float* __restrict__ di,
                                              float2* __restrict__ out) {
    int blk = blockIdx.x;
    int b  = blk / (Tn / TCH);
    int t0 = (blk % (Tn / TCH)) * TCH;
    int f = threadIdx.x;
    if (f >= Fn) return;

    float2 wv[8];
    const float2* wp = g_ws + ((size_t)(b*Fn + f))*8;
    #pragma unroll
    for (int c = 0; c < 8; c++) wv[c] = wp[c];

    #pragma unroll
    for (int tt = 0; tt < TCH; tt++) {
        int t = t0 + tt;
        size_t base = ((size_t)(b*Tn + t))*Cn*Fn + f;
        float accr = 0.f, acci = 0.f;
        #pragma unroll
        for (int c = 0; c < 8; c++) {
            float xr = dr[base + (size_t)c*Fn];
            float xi = di[base + (size_t)c*Fn];
            // conj(w) * x
            accr += wv[c].x*xr + wv[c].y*xi;
            acci += wv[c].x*xi - wv[c].y*xr;
        }
        out[(size_t)(b*Tn + t)*Fn + f] = make_float2(accr, acci);
    }
}

// ---------------- launcher ----------------
extern "C" void kernel_launch(void* const* d_in, const int* in_sizes, int n_in,
                              void* d_out, int out_size) {
    const float* dr    = (const float*)d_in[0];
    const float* di    = (const float*)d_in[1];
    const float* ms    = (const float*)d_in[2];
    const float* mn    = (const float*)d_in[3];
    const float* mlp_w = (const float*)d_in[4];
    const float* mlp_b = (const float*)d_in[5];
    const float* gvw   = (const float*)d_in[6];
    const float* gvb   = (const float*)d_in[7];
    (void)in_sizes; (void)n_in; (void)out_size;

    k_transpose<<<dim3(9, 16, Bn*Cn), dim3(32, 8)>>>(dr, di);
    k_psd<<<BF, 288>>>(ms, mn);
    k_att<<<Bn*Cn, An>>>(mlp_w, mlp_b, gvw, gvb);
    k_softmax<<<1, 64>>>();
    k_mvdr<<<BF, 128>>>();
    k_beam<<<Bn*(Tn/TCH), 288>>>(dr, di, (float2*)d_out);
}

// round 3
// speedup vs baseline: 2.6515x; 2.6515x over previous
#include <cuda_runtime.h>
#include <cuda_bf16.h>
#include <math.h>

#define Bn 8
#define Tn 512
#define Cn 8
#define Fn 257
#define An 320
#define BF (Bn*Fn)   // 2056

// ---------------- scratch (static device globals; no allocation) ----------------
__device__ float2 g_dataT[(size_t)Bn*Fn*Cn*Tn];   // (B,F,C,T) complex, 67.4 MB
__device__ float2 g_psd_s[(size_t)BF*Cn*Cn];      // (B,F,C,C)
__device__ float2 g_psd_n[(size_t)BF*Cn*Cn];
__device__ float  g_eval[Bn*Cn];
__device__ float  g_u[Bn*Cn];
__device__ float2 g_ws[(size_t)BF*Cn];            // (B,F,C)

// Hermitian pair tables (c<=e), 36 pairs, row-major over the upper triangle
__constant__ unsigned char cP[36] = {0,0,0,0,0,0,0,0, 1,1,1,1,1,1,1, 2,2,2,2,2,2,
                                     3,3,3,3,3, 4,4,4,4, 5,5,5, 6,6, 7};
__constant__ unsigned char cE[36] = {0,1,2,3,4,5,6,7, 1,2,3,4,5,6,7, 2,3,4,5,6,7,
                                     3,4,5,6,7, 4,5,6,7, 5,6,7, 6,7, 7};

// compile-time copies for register-indexed PSD loop
__device__ static constexpr int kP[36] = {0,0,0,0,0,0,0,0, 1,1,1,1,1,1,1, 2,2,2,2,2,2,
                                          3,3,3,3,3, 4,4,4,4, 5,5,5, 6,6, 7};
__device__ static constexpr int kE[36] = {0,1,2,3,4,5,6,7, 1,2,3,4,5,6,7, 2,3,4,5,6,7,
                                          3,4,5,6,7, 4,5,6,7, 5,6,7, 6,7, 7};

// ---------------- kernel 1: transpose (B,T,C,F) -> (B,F,C,T) float2 ----------------
__global__ void k_transpose(const float* __restrict__ dr, const float* __restrict__ di) {
    __shared__ float tr[32][33];
    __shared__ float ti[32][33];
    int bc = blockIdx.z;
    int b = bc >> 3, c = bc & 7;
    int f0 = blockIdx.x * 32, t0 = blockIdx.y * 32;
    int tx = threadIdx.x, ty = threadIdx.y;      // (32,8)

    #pragma unroll
    for (int r = 0; r < 32; r += 8) {
        int t = t0 + ty + r;
        int f = f0 + tx;
        if (f < Fn) {
            size_t idx = ((size_t)(b*Tn + t)*Cn + c)*Fn + f;
            tr[ty + r][tx] = dr[idx];
            ti[ty + r][tx] = di[idx];
        }
    }
    __syncthreads();
    #pragma unroll
    for (int r = 0; r < 32; r += 8) {
        int f = f0 + ty + r;
        int t = t0 + tx;
        if (f < Fn) {
            size_t o = ((size_t)(b*Fn + f)*Cn + c)*Tn + t;
            g_dataT[o] = make_float2(tr[tx][ty + r], ti[tx][ty + r]);
        }
    }
}

// ---------------- kernel 2: PSD per (b,f). 256 threads = 4 groups x 64 t-lanes ------
// Each thread loads all 8 channel values for its t once, computes 9 Hermitian
// pairs (compile-time indices) for both masks. LDS per 72 FLOPs: 72B.
template<int G>
__device__ __forceinline__ void psd_accum(
    const float2 (&xs)[Cn][Tn], const float* m0, const float* m1, int lane,
    float (&asr)[9], float (&asi)[9], float (&anr)[9], float (&ani)[9])
{
    for (int t = lane; t < Tn; t += 64) {
        float2 xv[8];
        #pragma unroll
        for (int c = 0; c < 8; c++) xv[c] = xs[c][t];
        float w0 = m0[t], w1 = m1[t];
        #pragma unroll
        for (int p = 0; p < 9; p++) {
            const int c = kP[G*9 + p];
            const int e = kE[G*9 + p];
            float pr = xv[c].x*xv[e].x + xv[c].y*xv[e].y;
            float pi = xv[c].y*xv[e].x - xv[c].x*xv[e].y;
            asr[p] += w0*pr; asi[p] += w0*pi;
            anr[p] += w1*pr; ani[p] += w1*pi;
        }
    }
}

__global__ __launch_bounds__(256) void k_psd(const float* __restrict__ ms,
                                             const float* __restrict__ mn) {
    __shared__ float2 xs[Cn][Tn];   // 32 KB, conflict-free float2 reads along t
    __shared__ float  m0[Tn];
    __shared__ float  m1[Tn];
    __shared__ float  r0s[8], r1s[8];
    __shared__ float  sInv0, sInv1;
    __shared__ float  red[4][2][9][4];   // group, warp-half, pair, comp

    int bf = blockIdx.x;
    int tid = threadIdx.x;

    // load x tile (coalesced float2)
    const float2* xp = g_dataT + (size_t)bf * Cn * Tn;
    #pragma unroll
    for (int k = 0; k < 16; k++)
        ((float2*)xs)[tid + 256*k] = xp[tid + 256*k];

    // masks: mean over c, then normalize over t
    const float* msp = ms + (size_t)bf * Cn * Tn;
    const float* mnp = mn + (size_t)bf * Cn * Tn;
    float tot0 = 0.f, tot1 = 0.f;
    #pragma unroll
    for (int kk = 0; kk < 2; kk++) {
        int t = tid + 256*kk;
        float s0 = 0.f, s1 = 0.f;
        #pragma unroll
        for (int c = 0; c < Cn; c++) { s0 += msp[c*Tn + t]; s1 += mnp[c*Tn + t]; }
        s0 *= 0.125f; s1 *= 0.125f;
        m0[t] = s0; m1[t] = s1;
        tot0 += s0; tot1 += s1;
    }
    #pragma unroll
    for (int o = 16; o; o >>= 1) {
        tot0 += __shfl_xor_sync(0xffffffffu, tot0, o);
        tot1 += __shfl_xor_sync(0xffffffffu, tot1, o);
    }
    int w = tid >> 5, lane32 = tid & 31;
    if (lane32 == 0) { r0s[w] = tot0; r1s[w] = tot1; }
    __syncthreads();
    if (tid == 0) {
        float a = 0.f, bsum = 0.f;
        #pragma unroll
        for (int k = 0; k < 8; k++) { a += r0s[k]; bsum += r1s[k]; }
        sInv0 = 1.f / (a + 1e-15f);
        sInv1 = 1.f / (bsum + 1e-15f);
    }
    __syncthreads();
    float iv0 = sInv0, iv1 = sInv1;
    #pragma unroll
    for (int kk = 0; kk < 2; kk++) {
        int t = tid + 256*kk;
        m0[t] *= iv0; m1[t] *= iv1;
    }
    __syncthreads();

    // pair accumulation
    int g = tid >> 6;         // 0..3 (whole warps share g)
    int lane = tid & 63;
    float asr[9], asi[9], anr[9], ani[9];
    #pragma unroll
    for (int p = 0; p < 9; p++) { asr[p]=0.f; asi[p]=0.f; anr[p]=0.f; ani[p]=0.f; }

    if      (g == 0) psd_accum<0>(xs, m0, m1, lane, asr, asi, anr, ani);
    else if (g == 1) psd_accum<1>(xs, m0, m1, lane, asr, asi, anr, ani);
    else if (g == 2) psd_accum<2>(xs, m0, m1, lane, asr, asi, anr, ani);
    else             psd_accum<3>(xs, m0, m1, lane, asr, asi, anr, ani);

    // reduce 64 lanes: intra-warp shuffle, then 2 warp-halves via smem
    #pragma unroll
    for (int p = 0; p < 9; p++) {
        #pragma unroll
        for (int o = 16; o; o >>= 1) {
            asr[p] += __shfl_xor_sync(0xffffffffu, asr[p], o);
            asi[p] += __shfl_xor_sync(0xffffffffu, asi[p], o);
            anr[p] += __shfl_xor_sync(0xffffffffu, anr[p], o);
            ani[p] += __shfl_xor_sync(0xffffffffu, ani[p], o);
        }
    }
    int half = (tid >> 5) & 1;
    if (lane32 == 0) {
        #pragma unroll
        for (int p = 0; p < 9; p++) {
            red[g][half][p][0] = asr[p];
            red[g][half][p][1] = asi[p];
            red[g][half][p][2] = anr[p];
            red[g][half][p][3] = ani[p];
        }
    }
    __syncthreads();

    if (tid < 36) {
        int gg = tid / 9, pp = tid % 9;
        float vsr = red[gg][0][pp][0] + red[gg][1][pp][0];
        float vsi = red[gg][0][pp][1] + red[gg][1][pp][1];
        float vnr = red[gg][0][pp][2] + red[gg][1][pp][2];
        float vni = red[gg][0][pp][3] + red[gg][1][pp][3];
        int c = cP[tid], e = cE[tid];
        size_t base = (size_t)bf * 64;
        g_psd_s[base + c*8 + e] = make_float2(vsr,  vsi);
        g_psd_s[base + e*8 + c] = make_float2(vsr, -vsi);
        g_psd_n[base + c*8 + e] = make_float2(vnr,  vni);
        g_psd_n[base + e*8 + c] = make_float2(vnr, -vni);
    }
}

// ---------------- kernel 3: attention MLP -> e[b,c]. 64 blocks x 320 threads --------
__global__ __launch_bounds__(An) void k_att(const float* __restrict__ mlp_w,
                                            const float* __restrict__ mlp_b,
                                            const float* __restrict__ gvw,
                                            const float* __restrict__ gvb) {
    __shared__ float feat[Fn];
    __shared__ float red[10];
    int b = blockIdx.x >> 3, c = blockIdx.x & 7;
    int tid = threadIdx.x;

    if (tid < Fn) {
        const float2* p = g_psd_s + ((size_t)(b*Fn + tid))*64 + c*8;
        float sr = 0.f, si = 0.f;
        #pragma unroll
        for (int e = 0; e < 8; e++) {
            if (e != c) { sr += p[e].x; si += p[e].y; }
        }
        feat[tid] = sqrtf(sr*sr + si*si) * (1.0f/7.0f);
    }
    __syncthreads();

    float dot = 0.f;
    for (int f = 0; f < Fn; f++) dot += feat[f] * mlp_w[f*An + tid];
    float h = tanhf(dot + mlp_b[tid]);
    float part = h * gvw[tid];

    #pragma unroll
    for (int o = 16; o; o >>= 1) part += __shfl_xor_sync(0xffffffffu, part, o);
    int w = tid >> 5, lane = tid & 31;
    if (lane == 0) red[w] = part;
    __syncthreads();
    if (tid == 0) {
        float s = 0.f;
        #pragma unroll
        for (int k = 0; k < 10; k++) s += red[k];
        g_eval[blockIdx.x] = s + gvb[0];
    }
}

// ---------------- kernel 4: softmax over channels. 1 block x 64 threads --------
__global__ void k_softmax() {
    int tid = threadIdx.x;                 // b = tid/8, c = tid%8
    float v = 2.0f * g_eval[tid];
    float mx = v;
    #pragma unroll
    for (int o = 1; o < 8; o <<= 1) mx = fmaxf(mx, __shfl_xor_sync(0xffffffffu, mx, o));
    float ex = expf(v - mx);
    float s = ex;
    #pragma unroll
    for (int o = 1; o < 8; o <<= 1) s += __shfl_xor_sync(0xffffffffu, s, o);
    g_u[tid] = ex / s;
}

// ---------------- kernel 5: MVDR solve, warp-synchronous fp32 Gauss-Jordan ----------
// One warp per (b,f): augmented [N | S] 8x16 complex, thread (i=lane>>2, q=lane&3)
// owns cols 4q..4q+3 of row i. 8 warps/block, zero __syncthreads.
__global__ __launch_bounds__(256) void k_mvdr() {
    const unsigned FULL = 0xffffffffu;
    int w = threadIdx.x >> 5;
    int bf = blockIdx.x * 8 + w;          // grid = 257
    int lane = threadIdx.x & 31;
    int i = lane >> 2;                    // row 0..7
    int q = lane & 3;                     // col group

    float ar[4], ai[4];
    #pragma unroll
    for (int m = 0; m < 4; m++) {
        int j = q*4 + m;
        float2 v = (j < 8) ? g_psd_n[(size_t)bf*64 + i*8 + j]
                           : g_psd_s[(size_t)bf*64 + i*8 + (j - 8)];
        ar[m] = v.x; ai[m] = v.y;
    }

    #pragma unroll
    for (int k = 0; k < 8; k++) {
        int psrc = (k << 2) | (k >> 2);
        float pvr = __shfl_sync(FULL, ar[k & 3], psrc);
        float pvi = __shfl_sync(FULL, ai[k & 3], psrc);
        float dd = 1.f / (pvr*pvr + pvi*pvi);
        float qr = pvr*dd, qi = -pvi*dd;
        if (i == k) {
            #pragma unroll
            for (int m = 0; m < 4; m++) {
                float trv = ar[m]*qr - ai[m]*qi;
                ai[m] = ar[m]*qi + ai[m]*qr;
                ar[m] = trv;
            }
        }
        // broadcast normalized pivot row for my col group
        float gr[4], gi[4];
        int rsrc = (k << 2) | q;
        #pragma unroll
        for (int m = 0; m < 4; m++) {
            gr[m] = __shfl_sync(FULL, ar[m], rsrc);
            gi[m] = __shfl_sync(FULL, ai[m], rsrc);
        }
        // my row's factor = a[i][k] (pre-elimination this iter)
        int fsrc = (i << 2) | (k >> 2);
        float fr = __shfl_sync(FULL, ar[k & 3], fsrc);
        float fi = __shfl_sync(FULL, ai[k & 3], fsrc);
        if (i != k) {
            #pragma unroll
            for (int m = 0; m < 4; m++) {
                ar[m] -= fr*gr[m] - fi*gi[m];
                ai[m] -= fr*gi[m] + fi*gr[m];
            }
        }
    }

    // trace of numerator = sum_i A[i][8+i]
    float tr_r = 0.f, tr_i = 0.f;
    if (q == ((8 + i) >> 2)) {
        int m = (8 + i) & 3;
        tr_r = ar[m]; tr_i = ai[m];
    }
    #pragma unroll
    for (int o = 16; o; o >>= 1) {
        tr_r += __shfl_xor_sync(FULL, tr_r, o);
        tr_i += __shfl_xor_sync(FULL, tr_i, o);
    }
    tr_r += 1e-15f;

    // ws[i] = (sum_c numerator[i][c] * u[c]) / trace
    int b = bf / Fn;
    float sr = 0.f, si = 0.f;
    if (q >= 2) {
        #pragma unroll
        for (int m = 0; m < 4; m++) {
            int c = (q - 2)*4 + m;
            float uu = g_u[b*8 + c];
            sr += ar[m]*uu; si += ai[m]*uu;
        }
    }
    sr += __shfl_xor_sync(FULL, sr, 1); si += __shfl_xor_sync(FULL, si, 1);
    sr += __shfl_xor_sync(FULL, sr, 2); si += __shfl_xor_sync(FULL, si, 2);
    if (q == 0) {
        float dd = 1.f / (tr_r*tr_r + tr_i*tr_i);
        float wr = (sr*tr_r + si*tr_i)*dd;
        float wi = (si*tr_r - sr*tr_i)*dd;
        g_ws[(size_t)bf*8 + i] = make_float2(wr, wi);
    }
}

// ---------------- kernel 6: beamforming -> output (B,T,F,2) ----------------
#define TCH 8
__global__ __launch_bounds__(288) void k_beam(const float* __restrict__ dr,
                                              const float* __restrict__ di,
                                              float2* __restrict__ out) {
    int blk = blockIdx.x;
    int b  = blk / (Tn / TCH);
    int t0 = (blk % (Tn / TCH)) * TCH;
    int f = threadIdx.x;
    if (f >= Fn) return;

    float2 wv[8];
    const float2* wp = g_ws + ((size_t)(b*Fn + f))*8;
    #pragma unroll
    for (int c = 0; c < 8; c++) wv[c] = wp[c];

    #pragma unroll
    for (int tt = 0; tt < TCH; tt++) {
        int t = t0 + tt;
        size_t base = ((size_t)(b*Tn + t))*Cn*Fn + f;
        float accr = 0.f, acci = 0.f;
        #pragma unroll
        for (int c = 0; c < 8; c++) {
            float xr = dr[base + (size_t)c*Fn];
            float xi = di[base + (size_t)c*Fn];
            // conj(w) * x
            accr += wv[c].x*xr + wv[c].y*xi;
            acci += wv[c].x*xi - wv[c].y*xr;
        }
        out[(size_t)(b*Tn + t)*Fn + f] = make_float2(accr, acci);
    }
}

// ---------------- launcher ----------------
extern "C" void kernel_launch(void* const* d_in, const int* in_sizes, int n_in,
                              void* d_out, int out_size) {
    const float* dr    = (const float*)d_in[0];
    const float* di    = (const float*)d_in[1];
    const float* ms    = (const float*)d_in[2];
    const float* mn    = (const float*)d_in[3];
    const float* mlp_w = (const float*)d_in[4];
    const float* mlp_b = (const float*)d_in[5];
    const float* gvw   = (const float*)d_in[6];
    const float* gvb   = (const float*)d_in[7];
    (void)in_sizes; (void)n_in; (void)out_size;

    k_transpose<<<dim3(9, 16, Bn*Cn), dim3(32, 8)>>>(dr, di);
    k_psd<<<BF, 256>>>(ms, mn);
    k_att<<<Bn*Cn, An>>>(mlp_w, mlp_b, gvw, gvb);
    k_softmax<<<1, 64>>>();
    k_mvdr<<<257, 256>>>();
    k_beam<<<Bn*(Tn/TCH), 288>>>(dr, di, (float2*)d_out);
}